// round 2
// baseline (speedup 1.0000x reference)
#include <cuda_runtime.h>

#define N_NODES 100000
#define N_EDGES 1600000
#define HIDDEN 64
#define N_LAYERS 4
#define BN_EPS 1e-5f

// ---------------- scratch (no allocation allowed) ----------------
__device__ float  g_agg[(size_t)N_NODES * HIDDEN];
__device__ float  g_z  [(size_t)N_NODES * HIDDEN];
__device__ double g_sum[HIDDEN];
__device__ double g_sq [HIDDEN];
__device__ float  g_scale[HIDDEN];
__device__ float  g_shift[HIDDEN];

// ---------------- init: h = node_feat ----------------
__global__ void copy_h_kernel(const float* __restrict__ src, float* __restrict__ dst) {
    int i = blockIdx.x * blockDim.x + threadIdx.x;
    if (i < N_NODES * HIDDEN / 4)
        ((float4*)dst)[i] = ((const float4*)src)[i];
}

// ---------------- zero agg + stats ----------------
__global__ void zero_kernel() {
    int i = blockIdx.x * blockDim.x + threadIdx.x;
    if (i < N_NODES * HIDDEN / 4)
        ((float4*)g_agg)[i] = make_float4(0.f, 0.f, 0.f, 0.f);
    if (i < HIDDEN) { g_sum[i] = 0.0; g_sq[i] = 0.0; }
}

// ---------------- scatter: agg[dst] += relu(h[src] + edge_feat@We + be) ----------------
// 16 threads per edge, float4 (4 features) per thread. e recomputed from edge_feat.
__global__ __launch_bounds__(256) void scatter_kernel(
    const float* __restrict__ h,
    const float* __restrict__ ef,
    const int*   __restrict__ src,
    const int*   __restrict__ dst,
    const float* __restrict__ We,
    const float* __restrict__ be)
{
    __shared__ float sWe[4 * HIDDEN];
    __shared__ float sbe[HIDDEN];
    int tid = threadIdx.x;
    for (int i = tid; i < 4 * HIDDEN; i += blockDim.x) sWe[i] = We[i];
    if (tid < HIDDEN) sbe[tid] = be[tid];
    __syncthreads();

    const int lane = tid & 15;   // feature group (4 floats)
    const int grp  = tid >> 4;   // edge slot within block (16 per 256 threads)
    const int f0   = lane * 4;

    for (int e = blockIdx.x * 16 + grp; e < N_EDGES; e += gridDim.x * 16) {
        int s = __ldg(src + e);
        int d = __ldg(dst + e);
        float4 efv = __ldg(((const float4*)ef) + e);

        float m[4];
        #pragma unroll
        for (int j = 0; j < 4; j++) {
            m[j] = sbe[f0 + j]
                 + efv.x * sWe[0 * HIDDEN + f0 + j]
                 + efv.y * sWe[1 * HIDDEN + f0 + j]
                 + efv.z * sWe[2 * HIDDEN + f0 + j]
                 + efv.w * sWe[3 * HIDDEN + f0 + j];
        }
        float4 hv = __ldg(((const float4*)(h + (size_t)s * HIDDEN)) + lane);
        m[0] = fmaxf(m[0] + hv.x, 0.f);
        m[1] = fmaxf(m[1] + hv.y, 0.f);
        m[2] = fmaxf(m[2] + hv.z, 0.f);
        m[3] = fmaxf(m[3] + hv.w, 0.f);

        float* a = g_agg + (size_t)d * HIDDEN + f0;
        asm volatile("red.global.add.v4.f32 [%0], {%1,%2,%3,%4};"
                     :: "l"(a), "f"(m[0]), "f"(m[1]), "f"(m[2]), "f"(m[3])
                     : "memory");
    }
}

// ---------------- MLP: z = relu((h+agg)@W1+b1)@W2+b2, plus per-feature stats ----------------
// 128 threads, 32 nodes/block. Each thread computes 4 nodes x 4 features (16 acc).
__global__ __launch_bounds__(128) void mlp_kernel(
    const float* __restrict__ h,
    const float* __restrict__ W1, const float* __restrict__ b1,
    const float* __restrict__ W2, const float* __restrict__ b2)
{
    __shared__ float sW[HIDDEN * HIDDEN];     // reused: W1 then W2 (16KB)
    __shared__ float sIn[32][HIDDEN + 1];     // z_in, later reused as stats scratch
    __shared__ float sT [32][HIDDEN + 1];     // relu intermediate

    const int tid = threadIdx.x;
    const int tf = tid & 15;     // feature group -> features [4tf, 4tf+4)
    const int tn = tid >> 4;     // node group (0..7) -> nodes [4tn, 4tn+4)
    const int f0 = tf * 4;
    const int n0 = tn * 4;
    const int node0 = blockIdx.x * 32;

    // load W1
    for (int i = tid; i < HIDDEN * HIDDEN; i += 128) sW[i] = __ldg(W1 + i);
    // load z_in = h + agg (32 rows x 64)
    for (int i = tid; i < 32 * HIDDEN / 4; i += 128) {
        int n = i >> 4, c = i & 15;
        float4 hv = __ldg(((const float4*)(h + (size_t)(node0 + n) * HIDDEN)) + c);
        float4 av = *(((const float4*)(g_agg + (size_t)(node0 + n) * HIDDEN)) + c);
        sIn[n][c * 4 + 0] = hv.x + av.x;
        sIn[n][c * 4 + 1] = hv.y + av.y;
        sIn[n][c * 4 + 2] = hv.z + av.z;
        sIn[n][c * 4 + 3] = hv.w + av.w;
    }
    __syncthreads();

    // matmul 1
    float acc[4][4];
    {
        float4 bias = __ldg(((const float4*)b1) + tf);
        #pragma unroll
        for (int i = 0; i < 4; i++) {
            acc[i][0] = bias.x; acc[i][1] = bias.y; acc[i][2] = bias.z; acc[i][3] = bias.w;
        }
    }
    #pragma unroll 4
    for (int k = 0; k < HIDDEN; k++) {
        float4 w = *(const float4*)(sW + k * HIDDEN + f0);
        #pragma unroll
        for (int i = 0; i < 4; i++) {
            float a = sIn[n0 + i][k];
            acc[i][0] += a * w.x; acc[i][1] += a * w.y;
            acc[i][2] += a * w.z; acc[i][3] += a * w.w;
        }
    }
    #pragma unroll
    for (int i = 0; i < 4; i++)
        #pragma unroll
        for (int j = 0; j < 4; j++)
            sT[n0 + i][f0 + j] = fmaxf(acc[i][j], 0.f);
    __syncthreads();

    // swap in W2
    for (int i = tid; i < HIDDEN * HIDDEN; i += 128) sW[i] = __ldg(W2 + i);
    __syncthreads();

    // matmul 2
    {
        float4 bias = __ldg(((const float4*)b2) + tf);
        #pragma unroll
        for (int i = 0; i < 4; i++) {
            acc[i][0] = bias.x; acc[i][1] = bias.y; acc[i][2] = bias.z; acc[i][3] = bias.w;
        }
    }
    #pragma unroll 4
    for (int k = 0; k < HIDDEN; k++) {
        float4 w = *(const float4*)(sW + k * HIDDEN + f0);
        #pragma unroll
        for (int i = 0; i < 4; i++) {
            float a = sT[n0 + i][k];
            acc[i][0] += a * w.x; acc[i][1] += a * w.y;
            acc[i][2] += a * w.z; acc[i][3] += a * w.w;
        }
    }

    // write z + per-thread stats partials
    float ps[4], pq[4];
    #pragma unroll
    for (int j = 0; j < 4; j++) { ps[j] = 0.f; pq[j] = 0.f; }
    #pragma unroll
    for (int i = 0; i < 4; i++) {
        float4 v = make_float4(acc[i][0], acc[i][1], acc[i][2], acc[i][3]);
        *(((float4*)(g_z + (size_t)(node0 + n0 + i) * HIDDEN)) + tf) = v;
        #pragma unroll
        for (int j = 0; j < 4; j++) { ps[j] += acc[i][j]; pq[j] += acc[i][j] * acc[i][j]; }
    }

    // block reduce over 8 node-groups (reuse sIn as scratch: [8][64] sums + [8][64] sqs)
    __syncthreads();
    float* rs = &sIn[0][0];          // 512 floats
    float* rq = &sIn[0][0] + 512;    // 512 floats
    #pragma unroll
    for (int j = 0; j < 4; j++) {
        rs[tn * HIDDEN + f0 + j] = ps[j];
        rq[tn * HIDDEN + f0 + j] = pq[j];
    }
    __syncthreads();
    if (tid < HIDDEN) {
        float s = 0.f, q = 0.f;
        #pragma unroll
        for (int g = 0; g < 8; g++) {
            s += rs[g * HIDDEN + tid];
            q += rq[g * HIDDEN + tid];
        }
        atomicAdd(&g_sum[tid], (double)s);
        atomicAdd(&g_sq[tid],  (double)q);
    }
}

// ---------------- BN prep: fold mean/var/gamma/beta into scale/shift ----------------
__global__ void bnprep_kernel(const float* __restrict__ gamma, const float* __restrict__ beta) {
    int f = threadIdx.x;
    if (f < HIDDEN) {
        double inv_n = 1.0 / (double)N_NODES;
        double mu  = g_sum[f] * inv_n;
        double var = g_sq[f] * inv_n - mu * mu;
        float rstd = rsqrtf((float)var + BN_EPS);
        float g = gamma[f];
        g_scale[f] = g * rstd;
        g_shift[f] = beta[f] - g * rstd * (float)mu;
    }
}

// ---------------- BN + ReLU + residual: h = relu(scale*z + shift) + h ----------------
__global__ __launch_bounds__(256) void bn_kernel(float* __restrict__ h) {
    int i = blockIdx.x * blockDim.x + threadIdx.x;
    if (i >= N_NODES * HIDDEN / 4) return;
    int c = i & 15;
    float4 z  = ((const float4*)g_z)[i];
    float4 hv = ((float4*)h)[i];
    float4 sc = *(((const float4*)g_scale) + c);
    float4 sh = *(((const float4*)g_shift) + c);
    hv.x += fmaxf(z.x * sc.x + sh.x, 0.f);
    hv.y += fmaxf(z.y * sc.y + sh.y, 0.f);
    hv.z += fmaxf(z.z * sc.z + sh.z, 0.f);
    hv.w += fmaxf(z.w * sc.w + sh.w, 0.f);
    ((float4*)h)[i] = hv;
}

// ---------------- launch ----------------
extern "C" void kernel_launch(void* const* d_in, const int* in_sizes, int n_in,
                              void* d_out, int out_size) {
    const float* node_feat = (const float*)d_in[0];
    const float* edge_feat = (const float*)d_in[1];
    const int*   src       = (const int*)  d_in[2];
    const int*   dst       = (const int*)  d_in[3];
    const float* We        = (const float*)d_in[4];
    const float* be        = (const float*)d_in[5];
    const float* W1        = (const float*)d_in[6];
    const float* b1        = (const float*)d_in[7];
    const float* W2        = (const float*)d_in[8];
    const float* b2        = (const float*)d_in[9];
    const float* gamma     = (const float*)d_in[10];
    const float* beta      = (const float*)d_in[11];
    float* h = (float*)d_out;

    const int ELEM4 = N_NODES * HIDDEN / 4;      // 1.6M
    const int VEC_BLOCKS = (ELEM4 + 255) / 256;  // 6250

    copy_h_kernel<<<VEC_BLOCKS, 256>>>(node_feat, h);

    for (int l = 0; l < N_LAYERS; l++) {
        zero_kernel<<<VEC_BLOCKS, 256>>>();
        scatter_kernel<<<2368, 256>>>(h, edge_feat, src, dst, We, be);
        mlp_kernel<<<N_NODES / 32, 128>>>(h,
                                          W1 + (size_t)l * HIDDEN * HIDDEN,
                                          b1 + (size_t)l * HIDDEN,
                                          W2 + (size_t)l * HIDDEN * HIDDEN,
                                          b2 + (size_t)l * HIDDEN);
        bnprep_kernel<<<1, 64>>>(gamma + (size_t)l * HIDDEN, beta + (size_t)l * HIDDEN);
        bn_kernel<<<VEC_BLOCKS, 256>>>(h);
    }
}